// round 9
// baseline (speedup 1.0000x reference)
#include <cuda_runtime.h>
#include <cstddef>

#define HH 128
#define WW 128
#define HWSZ (HH*WW)
#define EBN 8      // B(2) * 4 non-center frames, processed concurrently
#define CF 64
#define COFF 144
#define WSTEP (CF*CF*9)

// ---------------- scratch (device globals; no allocation) ----------------
__device__ float g_fea0[(size_t)EBN*CF*HWSZ];   // 32 MB
__device__ float g_fea1[(size_t)EBN*CF*HWSZ];   // 32 MB
__device__ float g_off [(size_t)EBN*COFF*HWSZ]; // 72 MB
__device__ float g_wT  [4*WSTEP];               // transposed dconv weights

__device__ __forceinline__ float* scratch_ptr(int sel) {
    return sel == 0 ? g_fea0 : (sel == 1 ? g_fea1 : g_off);
}

// eb -> (b, frame)
__device__ __forceinline__ void eb_map(int eb, int& b, int& fi) {
    b = eb >> 2;
    int f = eb & 3;
    fi = f + (f >= 2 ? 1 : 0);   // frames {0,1,3,4}
}

// ---------------- 3x3 SAME conv: 32x16 tile, 128 threads, 4 px/thread ----------------
// inMode: 0 = scratch[inSel] + eb*Cin*HW
//         1 = concat(ref, supp) read from pf (ext_in = pf base)
// outMode:0 = scratch[outSel] + eb*Cout*HW
//         1 = final output: ext_out + (b*5+fi)*3*HW
__global__ void __launch_bounds__(128) conv3x3_kernel(
    const float* __restrict__ ext_in,
    const float* __restrict__ w,
    const float* __restrict__ bias,
    float* __restrict__ ext_out,
    int Cin, int Cout, int inMode, int outMode, int inSel, int outSel)
{
    __shared__ float s_in[8][18][34];
    __shared__ float s_w[16][8][9];

    int tid = threadIdx.x;
    int tx = tid & 31, ty = tid >> 5;           // 32 x 4 threads, 4 rows/thread
    int ocg = (Cout + 15) >> 4;
    int eb = blockIdx.z / ocg;
    int ocBase = (blockIdx.z % ocg) << 4;
    int b, fi; eb_map(eb, b, fi);
    int ox0 = blockIdx.x * 32, oy0 = blockIdx.y * 16;

    const float* ref = nullptr; const float* supp = nullptr; const float* inb = nullptr;
    if (inMode == 1) {
        ref  = ext_in + (size_t)(b*5 + 2)  * CF * HWSZ;
        supp = ext_in + (size_t)(b*5 + fi) * CF * HWSZ;
    } else {
        inb = scratch_ptr(inSel) + (size_t)eb * Cin * HWSZ;
    }

    float acc[4][16];
    #pragma unroll
    for (int r = 0; r < 4; r++)
        #pragma unroll
        for (int i = 0; i < 16; i++) acc[r][i] = 0.f;

    for (int cb = 0; cb < Cin; cb += 8) {
        // cooperative load: 8 channels x (18 x 34) tile with zero-pad
        for (int idx = tid; idx < 8*18*34; idx += 128) {
            int ci = idx / (18*34);
            int rem = idx % (18*34);
            int r  = rem / 34;
            int c  = rem % 34;
            int gy = oy0 + r - 1;
            int gx = ox0 + c - 1;
            float v = 0.f;
            if (gy >= 0 && gy < HH && gx >= 0 && gx < WW) {
                int ch = cb + ci;
                const float* p;
                if (inMode == 1)
                    p = (ch < CF) ? (ref + (size_t)ch*HWSZ) : (supp + (size_t)(ch-CF)*HWSZ);
                else
                    p = inb + (size_t)ch*HWSZ;
                v = p[gy*WW + gx];
            }
            s_in[ci][r][c] = v;
        }
        // weights: 16 oc x 8 ci x 9
        for (int idx = tid; idx < 16*8*9; idx += 128) {
            int oc = idx / 72;
            int ci = (idx % 72) / 9;
            int k  = idx % 9;
            int o = ocBase + oc;
            float v = 0.f;
            if (o < Cout) v = w[((size_t)o*Cin + (cb+ci))*9 + k];
            s_w[oc][ci][k] = v;
        }
        __syncthreads();

        #pragma unroll
        for (int ci = 0; ci < 8; ci++) {
            #pragma unroll
            for (int kk = 0; kk < 9; kk++) {
                const int ky = kk / 3, kx = kk % 3;
                float v0 = s_in[ci][ty      + ky][tx + kx];
                float v1 = s_in[ci][ty + 4  + ky][tx + kx];
                float v2 = s_in[ci][ty + 8  + ky][tx + kx];
                float v3 = s_in[ci][ty + 12 + ky][tx + kx];
                #pragma unroll
                for (int oc = 0; oc < 16; oc++) {
                    float wv = s_w[oc][ci][kk];
                    acc[0][oc] += v0 * wv;
                    acc[1][oc] += v1 * wv;
                    acc[2][oc] += v2 * wv;
                    acc[3][oc] += v3 * wv;
                }
            }
        }
        __syncthreads();
    }

    int gx = ox0 + tx;
    float* ob;
    if (outMode == 1) ob = ext_out + (size_t)(b*5 + fi) * 3 * HWSZ;
    else              ob = scratch_ptr(outSel) + (size_t)eb * Cout * HWSZ;

    #pragma unroll
    for (int oc = 0; oc < 16; oc++) {
        int o = ocBase + oc;
        if (o < Cout) {
            float bv = bias[o];
            #pragma unroll
            for (int r = 0; r < 4; r++) {
                int gy = oy0 + ty + r*4;
                ob[(size_t)o*HWSZ + gy*WW + gx] = acc[r][oc] + bv;
            }
        }
    }
}

// ---------------- deformable conv (dg=8, Cg=8, K=3) ----------------
// xMode: 0 = x = scratch[xSel] + eb*64*HW ; 1 = x is supp read from pf (ext_x)
__global__ void __launch_bounds__(128) dconv_kernel(
    const float* __restrict__ ext_x,
    const float* __restrict__ bias,
    int xMode, int xSel, int wIdx, int outSel)
{
    int tid = threadIdx.x;
    int tx = tid & 15, ty = tid >> 4;          // 16 x 8 tile
    int eb = blockIdx.z;
    int b, fi; eb_map(eb, b, fi);
    int gx = blockIdx.x * 16 + tx;
    int gy = blockIdx.y * 8 + ty;
    int p = gy * WW + gx;

    const float* x = (xMode == 1) ? ext_x + (size_t)(b*5 + fi) * CF * HWSZ
                                  : scratch_ptr(xSel) + (size_t)eb * CF * HWSZ;
    const float* off = g_off + (size_t)eb * COFF * HWSZ + p;
    const float* wT  = g_wT + (size_t)wIdx * WSTEP;   // [(ci*9+k)*64 + o]

    float acc[64];
    #pragma unroll
    for (int o = 0; o < 64; o++) acc[o] = 0.f;

    #pragma unroll 1
    for (int g = 0; g < 8; g++) {
        #pragma unroll 1
        for (int k = 0; k < 9; k++) {
            float oy = off[(size_t)((g*9 + k)*2 + 0) * HWSZ];
            float ox = off[(size_t)((g*9 + k)*2 + 1) * HWSZ];
            float py = (float)gy + (float)(k/3 - 1) + oy;
            float px = (float)gx + (float)(k%3 - 1) + ox;
            float fy = floorf(py), fx = floorf(px);
            float wy = py - fy,  wx = px - fx;
            int iy0 = (int)fy, ix0 = (int)fx;
            int iy1 = iy0 + 1, ix1 = ix0 + 1;
            float my0 = (iy0 >= 0 && iy0 < HH) ? 1.f : 0.f;
            float my1 = (iy1 >= 0 && iy1 < HH) ? 1.f : 0.f;
            float mx0 = (ix0 >= 0 && ix0 < WW) ? 1.f : 0.f;
            float mx1 = (ix1 >= 0 && ix1 < WW) ? 1.f : 0.f;
            int cy0 = min(max(iy0, 0), HH-1);
            int cy1 = min(max(iy1, 0), HH-1);
            int cx0 = min(max(ix0, 0), WW-1);
            int cx1 = min(max(ix1, 0), WW-1);
            int p00 = cy0*WW + cx0, p01 = cy0*WW + cx1;
            int p10 = cy1*WW + cx0, p11 = cy1*WW + cx1;
            float w00 = (1.f - wy) * (1.f - wx) * my0 * mx0;
            float w01 = (1.f - wy) * wx         * my0 * mx1;
            float w10 = wy         * (1.f - wx) * my1 * mx0;
            float w11 = wy         * wx         * my1 * mx1;

            #pragma unroll
            for (int c = 0; c < 8; c++) {
                const float* ch = x + (size_t)(g*8 + c) * HWSZ;
                float s = ch[p00]*w00 + ch[p01]*w01 + ch[p10]*w10 + ch[p11]*w11;
                const float4* wtc = (const float4*)(wT + ((size_t)((g*8 + c)*9 + k)) * 64);
                #pragma unroll
                for (int o4 = 0; o4 < 16; o4++) {
                    float4 wv = wtc[o4];
                    acc[o4*4+0] += s * wv.x;
                    acc[o4*4+1] += s * wv.y;
                    acc[o4*4+2] += s * wv.z;
                    acc[o4*4+3] += s * wv.w;
                }
            }
        }
    }

    float* ob = scratch_ptr(outSel) + (size_t)eb * CF * HWSZ + p;
    #pragma unroll
    for (int o = 0; o < 64; o++) ob[(size_t)o * HWSZ] = acc[o] + bias[o];
}

// ---------------- dconv weight transpose: OIHW -> [(ci*9+k)][o], 4 at once ----------------
__global__ void wtrans_kernel(const float* __restrict__ w1, const float* __restrict__ w2,
                              const float* __restrict__ w3, const float* __restrict__ w4) {
    int i = blockIdx.x * 256 + threadIdx.x;
    int wIdx = blockIdx.y;
    const float* w = wIdx == 0 ? w1 : (wIdx == 1 ? w2 : (wIdx == 2 ? w3 : w4));
    if (i < 64*576) {
        int o = i / 576;
        int r = i % 576;
        g_wT[(size_t)wIdx*WSTEP + (size_t)r*64 + o] = w[i];
    }
}

// ---------------- center frame passthrough ----------------
__global__ void center_kernel(const float* __restrict__ xc, float* __restrict__ out) {
    int i = blockIdx.x * 256 + threadIdx.x;
    const int total = 2*3*HWSZ;
    if (i < total) {
        int b = i / (3*HWSZ);
        int r = i % (3*HWSZ);
        out[(size_t)(b*5 + 2)*3*HWSZ + r] = xc[i];
    }
}

// ---------------- launch (pure kernel launches; nothing else) ----------------
extern "C" void kernel_launch(void* const* d_in, const int* in_sizes, int n_in,
                              void* d_out, int out_size)
{
    const float* pf     = (const float*)d_in[0];
    const float* xc     = (const float*)d_in[1];
    const float* cr_w   = (const float*)d_in[2];
    const float* cr_b   = (const float*)d_in[3];
    const float* off1_w = (const float*)d_in[4];
    const float* off1_b = (const float*)d_in[5];
    const float* dc1_w  = (const float*)d_in[6];
    const float* dc1_b  = (const float*)d_in[7];
    const float* off2_w = (const float*)d_in[8];
    const float* off2_b = (const float*)d_in[9];
    const float* dc2_w  = (const float*)d_in[10];
    const float* dc2_b  = (const float*)d_in[11];
    const float* off3_w = (const float*)d_in[12];
    const float* off3_b = (const float*)d_in[13];
    const float* dc3_w  = (const float*)d_in[14];
    const float* dc3_b  = (const float*)d_in[15];
    const float* off4_w = (const float*)d_in[16];
    const float* off4_b = (const float*)d_in[17];
    const float* dc4_w  = (const float*)d_in[18];
    const float* dc4_b  = (const float*)d_in[19];
    const float* rec_w  = (const float*)d_in[20];
    const float* rec_b  = (const float*)d_in[21];
    float* out = (float*)d_out;

    dim3 tb(256);
    // transpose the 4 dconv weight tensors into g_wT (single launch)
    { dim3 g(144, 4); wtrans_kernel<<<g, tb>>>(dc1_w, dc2_w, dc3_w, dc4_w); }

    // center frame
    center_kernel<<<(2*3*HWSZ + 255)/256, tb>>>(xc, out);

    auto conv = [&](const float* ein, const float* w, const float* bsrc, float* eout,
                    int Cin, int Cout, int inMode, int outMode, int inSel, int outSel) {
        int ocg = (Cout + 15) >> 4;
        dim3 grid(WW/32, HH/16, EBN * ocg);
        conv3x3_kernel<<<grid, 128>>>(ein, w, bsrc, eout, Cin, Cout,
                                      inMode, outMode, inSel, outSel);
    };
    auto dconv = [&](const float* ex, const float* bsrc,
                     int xMode, int xSel, int wIdx, int outSel) {
        dim3 grid(WW/16, HH/8, EBN);
        dconv_kernel<<<grid, 128>>>(ex, bsrc, xMode, xSel, wIdx, outSel);
    };

    // fea0 = conv(concat(ref,supp))
    conv(pf, cr_w, cr_b, nullptr, 2*CF, CF, 1, 0, 0, 0);
    // off = off1(fea0); fea1 = dconv(fea0, off)
    conv(nullptr, off1_w, off1_b, nullptr, CF, COFF, 0, 0, 0, 2);
    dconv(nullptr, dc1_b, 0, 0, 0, 1);
    // off = off2(fea1); fea0 = dconv(fea1, off)
    conv(nullptr, off2_w, off2_b, nullptr, CF, COFF, 0, 0, 1, 2);
    dconv(nullptr, dc2_b, 0, 1, 1, 0);
    // off = off3(fea0); fea1 = dconv(supp, off)
    conv(nullptr, off3_w, off3_b, nullptr, CF, COFF, 0, 0, 0, 2);
    dconv(pf, dc3_b, 1, 0, 2, 1);
    // off = off4(fea1); fea0 = dconv(fea1, off)
    conv(nullptr, off4_w, off4_b, nullptr, CF, COFF, 0, 0, 1, 2);
    dconv(nullptr, dc4_b, 0, 1, 3, 0);
    // out = rec(fea0)
    conv(nullptr, rec_w, rec_b, out, CF, 3, 0, 1, 0, 0);
}

// round 12
// speedup vs baseline: 1.4932x; 1.4932x over previous
#include <cuda_runtime.h>
#include <cstddef>

#define HH 128
#define WW 128
#define HWSZ (HH*WW)
#define EBN 8      // B(2) * 4 non-center frames, processed concurrently
#define CF 64
#define COFF 144
#define WSTEP (CF*CF*9)

// ---------------- scratch (device globals; no allocation) ----------------
__device__ float g_fea0[(size_t)EBN*CF*HWSZ];   // 32 MB
__device__ float g_fea1[(size_t)EBN*CF*HWSZ];   // 32 MB
__device__ float g_off [(size_t)EBN*COFF*HWSZ]; // 72 MB
__device__ float g_wT  [4*WSTEP];               // transposed dconv weights

__device__ __forceinline__ float* scratch_ptr(int sel) {
    return sel == 0 ? g_fea0 : (sel == 1 ? g_fea1 : g_off);
}

// eb -> (b, frame)
__device__ __forceinline__ void eb_map(int eb, int& b, int& fi) {
    b = eb >> 2;
    int f = eb & 3;
    fi = f + (f >= 2 ? 1 : 0);   // frames {0,1,3,4}
}

// ---------------- 3x3 SAME conv: 32x16 tile, 128 threads, 4 px/thread ----------------
// inMode: 0 = scratch[inSel] + eb*Cin*HW
//         1 = concat(ref, supp) read from pf (ext_in = pf base)
// outMode:0 = scratch[outSel] + eb*Cout*HW
//         1 = final output: ext_out + (b*5+fi)*3*HW
__global__ void __launch_bounds__(128) conv3x3_kernel(
    const float* __restrict__ ext_in,
    const float* __restrict__ w,
    const float* __restrict__ bias,
    float* __restrict__ ext_out,
    int Cin, int Cout, int inMode, int outMode, int inSel, int outSel)
{
    __shared__ float s_in[8][18][34];
    __shared__ float s_w[16][8][9];

    int tid = threadIdx.x;
    int tx = tid & 31, ty = tid >> 5;           // 32 x 4 threads, 4 rows/thread
    int ocg = (Cout + 15) >> 4;
    int eb = blockIdx.z / ocg;
    int ocBase = (blockIdx.z % ocg) << 4;
    int b, fi; eb_map(eb, b, fi);
    int ox0 = blockIdx.x * 32, oy0 = blockIdx.y * 16;

    const float* ref = nullptr; const float* supp = nullptr; const float* inb = nullptr;
    if (inMode == 1) {
        ref  = ext_in + (size_t)(b*5 + 2)  * CF * HWSZ;
        supp = ext_in + (size_t)(b*5 + fi) * CF * HWSZ;
    } else {
        inb = scratch_ptr(inSel) + (size_t)eb * Cin * HWSZ;
    }

    float acc[4][16];
    #pragma unroll
    for (int r = 0; r < 4; r++)
        #pragma unroll
        for (int i = 0; i < 16; i++) acc[r][i] = 0.f;

    for (int cb = 0; cb < Cin; cb += 8) {
        // cooperative load: 8 channels x (18 x 34) tile with zero-pad
        for (int idx = tid; idx < 8*18*34; idx += 128) {
            int ci = idx / (18*34);
            int rem = idx % (18*34);
            int r  = rem / 34;
            int c  = rem % 34;
            int gy = oy0 + r - 1;
            int gx = ox0 + c - 1;
            float v = 0.f;
            if (gy >= 0 && gy < HH && gx >= 0 && gx < WW) {
                int ch = cb + ci;
                const float* p;
                if (inMode == 1)
                    p = (ch < CF) ? (ref + (size_t)ch*HWSZ) : (supp + (size_t)(ch-CF)*HWSZ);
                else
                    p = inb + (size_t)ch*HWSZ;
                v = p[gy*WW + gx];
            }
            s_in[ci][r][c] = v;
        }
        // weights: 16 oc x 8 ci x 9
        for (int idx = tid; idx < 16*8*9; idx += 128) {
            int oc = idx / 72;
            int ci = (idx % 72) / 9;
            int k  = idx % 9;
            int o = ocBase + oc;
            float v = 0.f;
            if (o < Cout) v = w[((size_t)o*Cin + (cb+ci))*9 + k];
            s_w[oc][ci][k] = v;
        }
        __syncthreads();

        #pragma unroll
        for (int ci = 0; ci < 8; ci++) {
            #pragma unroll
            for (int kk = 0; kk < 9; kk++) {
                const int ky = kk / 3, kx = kk % 3;
                float v0 = s_in[ci][ty      + ky][tx + kx];
                float v1 = s_in[ci][ty + 4  + ky][tx + kx];
                float v2 = s_in[ci][ty + 8  + ky][tx + kx];
                float v3 = s_in[ci][ty + 12 + ky][tx + kx];
                #pragma unroll
                for (int oc = 0; oc < 16; oc++) {
                    float wv = s_w[oc][ci][kk];
                    acc[0][oc] += v0 * wv;
                    acc[1][oc] += v1 * wv;
                    acc[2][oc] += v2 * wv;
                    acc[3][oc] += v3 * wv;
                }
            }
        }
        __syncthreads();
    }

    int gx = ox0 + tx;
    float* ob;
    if (outMode == 1) ob = ext_out + (size_t)(b*5 + fi) * 3 * HWSZ;
    else              ob = scratch_ptr(outSel) + (size_t)eb * Cout * HWSZ;

    #pragma unroll
    for (int oc = 0; oc < 16; oc++) {
        int o = ocBase + oc;
        if (o < Cout) {
            float bv = bias[o];
            #pragma unroll
            for (int r = 0; r < 4; r++) {
                int gy = oy0 + ty + r*4;
                ob[(size_t)o*HWSZ + gy*WW + gx] = acc[r][oc] + bv;
            }
        }
    }
}

// ---------------- deformable conv (dg=8, Cg=8, K=3), smem-staged weights ----------------
// 256 threads, 16x16 pixel tile (one pixel per thread)
// xMode: 0 = x = scratch[xSel] + eb*64*HW ; 1 = x is supp read from pf (ext_x)
__global__ void __launch_bounds__(256) dconv_kernel(
    const float* __restrict__ ext_x,
    const float* __restrict__ bias,
    int xMode, int xSel, int wIdx, int outSel)
{
    __shared__ float s_w[72*64];               // one group's weight slab, 18 KB

    int tid = threadIdx.x;
    int tx = tid & 15, ty = tid >> 4;          // 16 x 16 tile
    int eb = blockIdx.z;
    int b, fi; eb_map(eb, b, fi);
    int gx = blockIdx.x * 16 + tx;
    int gy = blockIdx.y * 16 + ty;
    int p = gy * WW + gx;

    const float* x = (xMode == 1) ? ext_x + (size_t)(b*5 + fi) * CF * HWSZ
                                  : scratch_ptr(xSel) + (size_t)eb * CF * HWSZ;
    const float* off = g_off + (size_t)eb * COFF * HWSZ + p;
    const float* wT  = g_wT + (size_t)wIdx * WSTEP;   // [(ci*9+k)*64 + o]

    float acc[64];
    #pragma unroll
    for (int o = 0; o < 64; o++) acc[o] = 0.f;

    #pragma unroll 1
    for (int g = 0; g < 8; g++) {
        // stage wT rows [g*72, g*72+72) x 64 into smem (1152 float4)
        __syncthreads();
        {
            const float4* src = (const float4*)(wT + (size_t)g * 72 * 64);
            float4* dst = (float4*)s_w;
            for (int i = tid; i < 1152; i += 256) dst[i] = src[i];
        }
        __syncthreads();

        #pragma unroll 1
        for (int k = 0; k < 9; k++) {
            float oy = off[(size_t)((g*9 + k)*2 + 0) * HWSZ];
            float ox = off[(size_t)((g*9 + k)*2 + 1) * HWSZ];
            float py = (float)gy + (float)(k/3 - 1) + oy;
            float px = (float)gx + (float)(k%3 - 1) + ox;
            float fy = floorf(py), fx = floorf(px);
            float wy = py - fy,  wx = px - fx;
            int iy0 = (int)fy, ix0 = (int)fx;
            int iy1 = iy0 + 1, ix1 = ix0 + 1;
            float my0 = (iy0 >= 0 && iy0 < HH) ? 1.f : 0.f;
            float my1 = (iy1 >= 0 && iy1 < HH) ? 1.f : 0.f;
            float mx0 = (ix0 >= 0 && ix0 < WW) ? 1.f : 0.f;
            float mx1 = (ix1 >= 0 && ix1 < WW) ? 1.f : 0.f;
            int cy0 = min(max(iy0, 0), HH-1);
            int cy1 = min(max(iy1, 0), HH-1);
            int cx0 = min(max(ix0, 0), WW-1);
            int cx1 = min(max(ix1, 0), WW-1);
            int p00 = cy0*WW + cx0, p01 = cy0*WW + cx1;
            int p10 = cy1*WW + cx0, p11 = cy1*WW + cx1;
            float w00 = (1.f - wy) * (1.f - wx) * my0 * mx0;
            float w01 = (1.f - wy) * wx         * my0 * mx1;
            float w10 = wy         * (1.f - wx) * my1 * mx0;
            float w11 = wy         * wx         * my1 * mx1;

            #pragma unroll
            for (int c = 0; c < 8; c++) {
                const float* ch = x + (size_t)(g*8 + c) * HWSZ;
                float s = ch[p00]*w00 + ch[p01]*w01 + ch[p10]*w10 + ch[p11]*w11;
                const float4* wtc = (const float4*)(s_w + (c*9 + k) * 64);
                #pragma unroll
                for (int o4 = 0; o4 < 16; o4++) {
                    float4 wv = wtc[o4];
                    acc[o4*4+0] += s * wv.x;
                    acc[o4*4+1] += s * wv.y;
                    acc[o4*4+2] += s * wv.z;
                    acc[o4*4+3] += s * wv.w;
                }
            }
        }
    }

    float* ob = scratch_ptr(outSel) + (size_t)eb * CF * HWSZ + p;
    #pragma unroll
    for (int o = 0; o < 64; o++) ob[(size_t)o * HWSZ] = acc[o] + bias[o];
}

// ---------------- dconv weight transpose: OIHW -> [(ci*9+k)][o], 4 at once ----------------
__global__ void wtrans_kernel(const float* __restrict__ w1, const float* __restrict__ w2,
                              const float* __restrict__ w3, const float* __restrict__ w4) {
    int i = blockIdx.x * 256 + threadIdx.x;
    int wIdx = blockIdx.y;
    const float* w = wIdx == 0 ? w1 : (wIdx == 1 ? w2 : (wIdx == 2 ? w3 : w4));
    if (i < 64*576) {
        int o = i / 576;
        int r = i % 576;
        g_wT[(size_t)wIdx*WSTEP + (size_t)r*64 + o] = w[i];
    }
}

// ---------------- center frame passthrough ----------------
__global__ void center_kernel(const float* __restrict__ xc, float* __restrict__ out) {
    int i = blockIdx.x * 256 + threadIdx.x;
    const int total = 2*3*HWSZ;
    if (i < total) {
        int b = i / (3*HWSZ);
        int r = i % (3*HWSZ);
        out[(size_t)(b*5 + 2)*3*HWSZ + r] = xc[i];
    }
}

// ---------------- launch (pure kernel launches; nothing else) ----------------
extern "C" void kernel_launch(void* const* d_in, const int* in_sizes, int n_in,
                              void* d_out, int out_size)
{
    const float* pf     = (const float*)d_in[0];
    const float* xc     = (const float*)d_in[1];
    const float* cr_w   = (const float*)d_in[2];
    const float* cr_b   = (const float*)d_in[3];
    const float* off1_w = (const float*)d_in[4];
    const float* off1_b = (const float*)d_in[5];
    const float* dc1_w  = (const float*)d_in[6];
    const float* dc1_b  = (const float*)d_in[7];
    const float* off2_w = (const float*)d_in[8];
    const float* off2_b = (const float*)d_in[9];
    const float* dc2_w  = (const float*)d_in[10];
    const float* dc2_b  = (const float*)d_in[11];
    const float* off3_w = (const float*)d_in[12];
    const float* off3_b = (const float*)d_in[13];
    const float* dc3_w  = (const float*)d_in[14];
    const float* dc3_b  = (const float*)d_in[15];
    const float* off4_w = (const float*)d_in[16];
    const float* off4_b = (const float*)d_in[17];
    const float* dc4_w  = (const float*)d_in[18];
    const float* dc4_b  = (const float*)d_in[19];
    const float* rec_w  = (const float*)d_in[20];
    const float* rec_b  = (const float*)d_in[21];
    float* out = (float*)d_out;

    dim3 tb(256);
    // transpose the 4 dconv weight tensors into g_wT (single launch)
    { dim3 g(144, 4); wtrans_kernel<<<g, tb>>>(dc1_w, dc2_w, dc3_w, dc4_w); }

    // center frame
    center_kernel<<<(2*3*HWSZ + 255)/256, tb>>>(xc, out);

    auto conv = [&](const float* ein, const float* w, const float* bsrc, float* eout,
                    int Cin, int Cout, int inMode, int outMode, int inSel, int outSel) {
        int ocg = (Cout + 15) >> 4;
        dim3 grid(WW/32, HH/16, EBN * ocg);
        conv3x3_kernel<<<grid, 128>>>(ein, w, bsrc, eout, Cin, Cout,
                                      inMode, outMode, inSel, outSel);
    };
    auto dconv = [&](const float* ex, const float* bsrc,
                     int xMode, int xSel, int wIdx, int outSel) {
        dim3 grid(WW/16, HH/16, EBN);
        dconv_kernel<<<grid, 256>>>(ex, bsrc, xMode, xSel, wIdx, outSel);
    };

    // fea0 = conv(concat(ref,supp))
    conv(pf, cr_w, cr_b, nullptr, 2*CF, CF, 1, 0, 0, 0);
    // off = off1(fea0); fea1 = dconv(fea0, off)
    conv(nullptr, off1_w, off1_b, nullptr, CF, COFF, 0, 0, 0, 2);
    dconv(nullptr, dc1_b, 0, 0, 0, 1);
    // off = off2(fea1); fea0 = dconv(fea1, off)
    conv(nullptr, off2_w, off2_b, nullptr, CF, COFF, 0, 0, 1, 2);
    dconv(nullptr, dc2_b, 0, 1, 1, 0);
    // off = off3(fea0); fea1 = dconv(supp, off)
    conv(nullptr, off3_w, off3_b, nullptr, CF, COFF, 0, 0, 0, 2);
    dconv(pf, dc3_b, 1, 0, 2, 1);
    // off = off4(fea1); fea0 = dconv(fea1, off)
    conv(nullptr, off4_w, off4_b, nullptr, CF, COFF, 0, 0, 1, 2);
    dconv(nullptr, dc4_b, 0, 1, 3, 0);
    // out = rec(fea0)
    conv(nullptr, rec_w, rec_b, out, CF, 3, 0, 1, 0, 0);
}

// round 13
// speedup vs baseline: 1.5197x; 1.0178x over previous
#include <cuda_runtime.h>
#include <cstddef>

#define HH 128
#define WW 128
#define HWSZ (HH*WW)
#define EBN 8      // B(2) * 4 non-center frames, processed concurrently
#define CF 64
#define COFF 144
#define WSTEP (CF*CF*9)

// ---------------- scratch (device globals; no allocation) ----------------
__device__ float g_fea0[(size_t)EBN*CF*HWSZ];   // 32 MB
__device__ float g_fea1[(size_t)EBN*CF*HWSZ];   // 32 MB
__device__ float g_off [(size_t)EBN*COFF*HWSZ]; // 72 MB
__device__ float g_wT  [4*WSTEP];               // transposed dconv weights

__device__ __forceinline__ float* scratch_ptr(int sel) {
    return sel == 0 ? g_fea0 : (sel == 1 ? g_fea1 : g_off);
}

// eb -> (b, frame)
__device__ __forceinline__ void eb_map(int eb, int& b, int& fi) {
    b = eb >> 2;
    int f = eb & 3;
    fi = f + (f >= 2 ? 1 : 0);   // frames {0,1,3,4}
}

// ---------------- 3x3 SAME conv: 32x16 tile, 128 threads, 4 px/thread ----------------
// weights staged as [ci][kk][oc] so 16-oc reads are one float4 x4 (LDS.128 broadcast)
// inMode: 0 = scratch[inSel] + eb*Cin*HW
//         1 = concat(ref, supp) read from pf (ext_in = pf base)
// outMode:0 = scratch[outSel] + eb*Cout*HW
//         1 = final output: ext_out + (b*5+fi)*3*HW
__global__ void __launch_bounds__(128) conv3x3_kernel(
    const float* __restrict__ ext_in,
    const float* __restrict__ w,
    const float* __restrict__ bias,
    float* __restrict__ ext_out,
    int Cin, int Cout, int inMode, int outMode, int inSel, int outSel)
{
    __shared__ float s_in[8][18][34];
    __shared__ __align__(16) float s_w[8][9][16];   // [ci][kk][oc]

    int tid = threadIdx.x;
    int tx = tid & 31, ty = tid >> 5;           // 32 x 4 threads, 4 rows/thread
    int ocg = (Cout + 15) >> 4;
    int eb = blockIdx.z / ocg;
    int ocBase = (blockIdx.z % ocg) << 4;
    int b, fi; eb_map(eb, b, fi);
    int ox0 = blockIdx.x * 32, oy0 = blockIdx.y * 16;

    const float* ref = nullptr; const float* supp = nullptr; const float* inb = nullptr;
    if (inMode == 1) {
        ref  = ext_in + (size_t)(b*5 + 2)  * CF * HWSZ;
        supp = ext_in + (size_t)(b*5 + fi) * CF * HWSZ;
    } else {
        inb = scratch_ptr(inSel) + (size_t)eb * Cin * HWSZ;
    }

    float acc[4][16];
    #pragma unroll
    for (int r = 0; r < 4; r++)
        #pragma unroll
        for (int i = 0; i < 16; i++) acc[r][i] = 0.f;

    for (int cb = 0; cb < Cin; cb += 8) {
        // cooperative load: 8 channels x (18 x 34) tile with zero-pad
        for (int idx = tid; idx < 8*18*34; idx += 128) {
            int ci = idx / (18*34);
            int rem = idx % (18*34);
            int r  = rem / 34;
            int c  = rem % 34;
            int gy = oy0 + r - 1;
            int gx = ox0 + c - 1;
            float v = 0.f;
            if (gy >= 0 && gy < HH && gx >= 0 && gx < WW) {
                int ch = cb + ci;
                const float* p;
                if (inMode == 1)
                    p = (ch < CF) ? (ref + (size_t)ch*HWSZ) : (supp + (size_t)(ch-CF)*HWSZ);
                else
                    p = inb + (size_t)ch*HWSZ;
                v = p[gy*WW + gx];
            }
            s_in[ci][r][c] = v;
        }
        // weights: [ci][k][oc] layout, 8*9*16 = 1152 entries
        for (int idx = tid; idx < 8*9*16; idx += 128) {
            int ci = idx / (9*16);
            int k  = (idx / 16) % 9;
            int oc = idx % 16;
            int o = ocBase + oc;
            float v = 0.f;
            if (o < Cout) v = w[((size_t)o*Cin + (cb+ci))*9 + k];
            s_w[ci][k][oc] = v;
        }
        __syncthreads();

        #pragma unroll
        for (int ci = 0; ci < 8; ci++) {
            #pragma unroll
            for (int kk = 0; kk < 9; kk++) {
                const int ky = kk / 3, kx = kk % 3;
                float v0 = s_in[ci][ty      + ky][tx + kx];
                float v1 = s_in[ci][ty + 4  + ky][tx + kx];
                float v2 = s_in[ci][ty + 8  + ky][tx + kx];
                float v3 = s_in[ci][ty + 12 + ky][tx + kx];
                const float4* wp = (const float4*)&s_w[ci][kk][0];
                #pragma unroll
                for (int q = 0; q < 4; q++) {
                    float4 wv = wp[q];
                    acc[0][q*4+0] += v0 * wv.x; acc[0][q*4+1] += v0 * wv.y;
                    acc[0][q*4+2] += v0 * wv.z; acc[0][q*4+3] += v0 * wv.w;
                    acc[1][q*4+0] += v1 * wv.x; acc[1][q*4+1] += v1 * wv.y;
                    acc[1][q*4+2] += v1 * wv.z; acc[1][q*4+3] += v1 * wv.w;
                    acc[2][q*4+0] += v2 * wv.x; acc[2][q*4+1] += v2 * wv.y;
                    acc[2][q*4+2] += v2 * wv.z; acc[2][q*4+3] += v2 * wv.w;
                    acc[3][q*4+0] += v3 * wv.x; acc[3][q*4+1] += v3 * wv.y;
                    acc[3][q*4+2] += v3 * wv.z; acc[3][q*4+3] += v3 * wv.w;
                }
            }
        }
        __syncthreads();
    }

    int gx = ox0 + tx;
    float* ob;
    if (outMode == 1) ob = ext_out + (size_t)(b*5 + fi) * 3 * HWSZ;
    else              ob = scratch_ptr(outSel) + (size_t)eb * Cout * HWSZ;

    #pragma unroll
    for (int oc = 0; oc < 16; oc++) {
        int o = ocBase + oc;
        if (o < Cout) {
            float bv = bias[o];
            #pragma unroll
            for (int r = 0; r < 4; r++) {
                int gy = oy0 + ty + r*4;
                ob[(size_t)o*HWSZ + gy*WW + gx] = acc[r][oc] + bv;
            }
        }
    }
}

// ---------------- deformable conv (dg=8, Cg=8, K=3), smem-staged weights ----------------
// 256 threads, 16x16 pixel tile (one pixel per thread)
// xMode: 0 = x = scratch[xSel] + eb*64*HW ; 1 = x is supp read from pf (ext_x)
__global__ void __launch_bounds__(256) dconv_kernel(
    const float* __restrict__ ext_x,
    const float* __restrict__ bias,
    int xMode, int xSel, int wIdx, int outSel)
{
    __shared__ float s_w[72*64];               // one group's weight slab, 18 KB

    int tid = threadIdx.x;
    int tx = tid & 15, ty = tid >> 4;          // 16 x 16 tile
    int eb = blockIdx.z;
    int b, fi; eb_map(eb, b, fi);
    int gx = blockIdx.x * 16 + tx;
    int gy = blockIdx.y * 16 + ty;
    int p = gy * WW + gx;

    const float* x = (xMode == 1) ? ext_x + (size_t)(b*5 + fi) * CF * HWSZ
                                  : scratch_ptr(xSel) + (size_t)eb * CF * HWSZ;
    const float* off = g_off + (size_t)eb * COFF * HWSZ + p;
    const float* wT  = g_wT + (size_t)wIdx * WSTEP;   // [(ci*9+k)*64 + o]

    float acc[64];
    #pragma unroll
    for (int o = 0; o < 64; o++) acc[o] = 0.f;

    #pragma unroll 1
    for (int g = 0; g < 8; g++) {
        // stage wT rows [g*72, g*72+72) x 64 into smem (1152 float4)
        __syncthreads();
        {
            const float4* src = (const float4*)(wT + (size_t)g * 72 * 64);
            float4* dst = (float4*)s_w;
            for (int i = tid; i < 1152; i += 256) dst[i] = src[i];
        }
        __syncthreads();

        #pragma unroll 1
        for (int k = 0; k < 9; k++) {
            float oy = off[(size_t)((g*9 + k)*2 + 0) * HWSZ];
            float ox = off[(size_t)((g*9 + k)*2 + 1) * HWSZ];
            float py = (float)gy + (float)(k/3 - 1) + oy;
            float px = (float)gx + (float)(k%3 - 1) + ox;
            float fy = floorf(py), fx = floorf(px);
            float wy = py - fy,  wx = px - fx;
            int iy0 = (int)fy, ix0 = (int)fx;
            int iy1 = iy0 + 1, ix1 = ix0 + 1;
            float my0 = (iy0 >= 0 && iy0 < HH) ? 1.f : 0.f;
            float my1 = (iy1 >= 0 && iy1 < HH) ? 1.f : 0.f;
            float mx0 = (ix0 >= 0 && ix0 < WW) ? 1.f : 0.f;
            float mx1 = (ix1 >= 0 && ix1 < WW) ? 1.f : 0.f;
            int cy0 = min(max(iy0, 0), HH-1);
            int cy1 = min(max(iy1, 0), HH-1);
            int cx0 = min(max(ix0, 0), WW-1);
            int cx1 = min(max(ix1, 0), WW-1);
            int p00 = cy0*WW + cx0, p01 = cy0*WW + cx1;
            int p10 = cy1*WW + cx0, p11 = cy1*WW + cx1;
            float w00 = (1.f - wy) * (1.f - wx) * my0 * mx0;
            float w01 = (1.f - wy) * wx         * my0 * mx1;
            float w10 = wy         * (1.f - wx) * my1 * mx0;
            float w11 = wy         * wx         * my1 * mx1;

            #pragma unroll
            for (int c = 0; c < 8; c++) {
                const float* ch = x + (size_t)(g*8 + c) * HWSZ;
                float s = ch[p00]*w00 + ch[p01]*w01 + ch[p10]*w10 + ch[p11]*w11;
                const float4* wtc = (const float4*)(s_w + (c*9 + k) * 64);
                #pragma unroll
                for (int o4 = 0; o4 < 16; o4++) {
                    float4 wv = wtc[o4];
                    acc[o4*4+0] += s * wv.x;
                    acc[o4*4+1] += s * wv.y;
                    acc[o4*4+2] += s * wv.z;
                    acc[o4*4+3] += s * wv.w;
                }
            }
        }
    }

    float* ob = scratch_ptr(outSel) + (size_t)eb * CF * HWSZ + p;
    #pragma unroll
    for (int o = 0; o < 64; o++) ob[(size_t)o * HWSZ] = acc[o] + bias[o];
}

// ---------------- dconv weight transpose: OIHW -> [(ci*9+k)][o], 4 at once ----------------
__global__ void wtrans_kernel(const float* __restrict__ w1, const float* __restrict__ w2,
                              const float* __restrict__ w3, const float* __restrict__ w4) {
    int i = blockIdx.x * 256 + threadIdx.x;
    int wIdx = blockIdx.y;
    const float* w = wIdx == 0 ? w1 : (wIdx == 1 ? w2 : (wIdx == 2 ? w3 : w4));
    if (i < 64*576) {
        int o = i / 576;
        int r = i % 576;
        g_wT[(size_t)wIdx*WSTEP + (size_t)r*64 + o] = w[i];
    }
}

// ---------------- center frame passthrough ----------------
__global__ void center_kernel(const float* __restrict__ xc, float* __restrict__ out) {
    int i = blockIdx.x * 256 + threadIdx.x;
    const int total = 2*3*HWSZ;
    if (i < total) {
        int b = i / (3*HWSZ);
        int r = i % (3*HWSZ);
        out[(size_t)(b*5 + 2)*3*HWSZ + r] = xc[i];
    }
}

// ---------------- launch (pure kernel launches; nothing else) ----------------
extern "C" void kernel_launch(void* const* d_in, const int* in_sizes, int n_in,
                              void* d_out, int out_size)
{
    const float* pf     = (const float*)d_in[0];
    const float* xc     = (const float*)d_in[1];
    const float* cr_w   = (const float*)d_in[2];
    const float* cr_b   = (const float*)d_in[3];
    const float* off1_w = (const float*)d_in[4];
    const float* off1_b = (const float*)d_in[5];
    const float* dc1_w  = (const float*)d_in[6];
    const float* dc1_b  = (const float*)d_in[7];
    const float* off2_w = (const float*)d_in[8];
    const float* off2_b = (const float*)d_in[9];
    const float* dc2_w  = (const float*)d_in[10];
    const float* dc2_b  = (const float*)d_in[11];
    const float* off3_w = (const float*)d_in[12];
    const float* off3_b = (const float*)d_in[13];
    const float* dc3_w  = (const float*)d_in[14];
    const float* dc3_b  = (const float*)d_in[15];
    const float* off4_w = (const float*)d_in[16];
    const float* off4_b = (const float*)d_in[17];
    const float* dc4_w  = (const float*)d_in[18];
    const float* dc4_b  = (const float*)d_in[19];
    const float* rec_w  = (const float*)d_in[20];
    const float* rec_b  = (const float*)d_in[21];
    float* out = (float*)d_out;

    dim3 tb(256);
    // transpose the 4 dconv weight tensors into g_wT (single launch)
    { dim3 g(144, 4); wtrans_kernel<<<g, tb>>>(dc1_w, dc2_w, dc3_w, dc4_w); }

    // center frame
    center_kernel<<<(2*3*HWSZ + 255)/256, tb>>>(xc, out);

    auto conv = [&](const float* ein, const float* w, const float* bsrc, float* eout,
                    int Cin, int Cout, int inMode, int outMode, int inSel, int outSel) {
        int ocg = (Cout + 15) >> 4;
        dim3 grid(WW/32, HH/16, EBN * ocg);
        conv3x3_kernel<<<grid, 128>>>(ein, w, bsrc, eout, Cin, Cout,
                                      inMode, outMode, inSel, outSel);
    };
    auto dconv = [&](const float* ex, const float* bsrc,
                     int xMode, int xSel, int wIdx, int outSel) {
        dim3 grid(WW/16, HH/16, EBN);
        dconv_kernel<<<grid, 256>>>(ex, bsrc, xMode, xSel, wIdx, outSel);
    };

    // fea0 = conv(concat(ref,supp))
    conv(pf, cr_w, cr_b, nullptr, 2*CF, CF, 1, 0, 0, 0);
    // off = off1(fea0); fea1 = dconv(fea0, off)
    conv(nullptr, off1_w, off1_b, nullptr, CF, COFF, 0, 0, 0, 2);
    dconv(nullptr, dc1_b, 0, 0, 0, 1);
    // off = off2(fea1); fea0 = dconv(fea1, off)
    conv(nullptr, off2_w, off2_b, nullptr, CF, COFF, 0, 0, 1, 2);
    dconv(nullptr, dc2_b, 0, 1, 1, 0);
    // off = off3(fea0); fea1 = dconv(supp, off)
    conv(nullptr, off3_w, off3_b, nullptr, CF, COFF, 0, 0, 0, 2);
    dconv(pf, dc3_b, 1, 0, 2, 1);
    // off = off4(fea1); fea0 = dconv(fea1, off)
    conv(nullptr, off4_w, off4_b, nullptr, CF, COFF, 0, 0, 1, 2);
    dconv(nullptr, dc4_b, 0, 1, 3, 0);
    // out = rec(fea0)
    conv(nullptr, rec_w, rec_b, out, CF, 3, 0, 1, 0, 0);
}

// round 14
// speedup vs baseline: 1.8556x; 1.2210x over previous
#include <cuda_runtime.h>
#include <cstddef>

#define HH 128
#define WW 128
#define HWSZ (HH*WW)
#define EBN 8      // B(2) * 4 non-center frames, processed concurrently
#define CF 64
#define COFF 144
#define WSTEP (CF*CF*9)

// packed fp32x2 FMA: d = a*b + d  (two independent fp32 FMAs, .rn, one FFMA2)
#define FMA2(d, a, b) \
    asm("fma.rn.f32x2 %0, %1, %2, %0;" : "+l"(d) : "l"(a), "l"(b))
#define PACK2(d, v) \
    asm("mov.b64 %0, {%1, %1};" : "=l"(d) : "r"(__float_as_uint(v)))
#define UNPACK2(lo, hi, v) \
    asm("mov.b64 {%0, %1}, %2;" : "=r"(lo), "=r"(hi) : "l"(v))

// ---------------- scratch (device globals; no allocation) ----------------
__device__ float g_fea0[(size_t)EBN*CF*HWSZ];   // 32 MB
__device__ float g_fea1[(size_t)EBN*CF*HWSZ];   // 32 MB
__device__ float g_off [(size_t)EBN*COFF*HWSZ]; // 72 MB
__device__ float g_wT  [4*WSTEP];               // transposed dconv weights

__device__ __forceinline__ float* scratch_ptr(int sel) {
    return sel == 0 ? g_fea0 : (sel == 1 ? g_fea1 : g_off);
}

// eb -> (b, frame)
__device__ __forceinline__ void eb_map(int eb, int& b, int& fi) {
    b = eb >> 2;
    int f = eb & 3;
    fi = f + (f >= 2 ? 1 : 0);   // frames {0,1,3,4}
}

// ---------------- 3x3 SAME conv: 32x16 tile, 128 threads, 4 px/thread ----------------
// weights staged as [ci][kk][oc]; inner loop uses packed f32x2 FMA over oc pairs
__global__ void __launch_bounds__(128) conv3x3_kernel(
    const float* __restrict__ ext_in,
    const float* __restrict__ w,
    const float* __restrict__ bias,
    float* __restrict__ ext_out,
    int Cin, int Cout, int inMode, int outMode, int inSel, int outSel)
{
    __shared__ float s_in[8][18][34];
    __shared__ __align__(16) float s_w[8][9][16];   // [ci][kk][oc]

    int tid = threadIdx.x;
    int tx = tid & 31, ty = tid >> 5;           // 32 x 4 threads, 4 rows/thread
    int ocg = (Cout + 15) >> 4;
    int eb = blockIdx.z / ocg;
    int ocBase = (blockIdx.z % ocg) << 4;
    int b, fi; eb_map(eb, b, fi);
    int ox0 = blockIdx.x * 32, oy0 = blockIdx.y * 16;

    const float* ref = nullptr; const float* supp = nullptr; const float* inb = nullptr;
    if (inMode == 1) {
        ref  = ext_in + (size_t)(b*5 + 2)  * CF * HWSZ;
        supp = ext_in + (size_t)(b*5 + fi) * CF * HWSZ;
    } else {
        inb = scratch_ptr(inSel) + (size_t)eb * Cin * HWSZ;
    }

    unsigned long long accp[4][8];
    #pragma unroll
    for (int r = 0; r < 4; r++)
        #pragma unroll
        for (int i = 0; i < 8; i++) accp[r][i] = 0ULL;

    for (int cb = 0; cb < Cin; cb += 8) {
        // cooperative load: 8 channels x (18 x 34) tile with zero-pad
        for (int idx = tid; idx < 8*18*34; idx += 128) {
            int ci = idx / (18*34);
            int rem = idx % (18*34);
            int r  = rem / 34;
            int c  = rem % 34;
            int gy = oy0 + r - 1;
            int gx = ox0 + c - 1;
            float v = 0.f;
            if (gy >= 0 && gy < HH && gx >= 0 && gx < WW) {
                int ch = cb + ci;
                const float* p;
                if (inMode == 1)
                    p = (ch < CF) ? (ref + (size_t)ch*HWSZ) : (supp + (size_t)(ch-CF)*HWSZ);
                else
                    p = inb + (size_t)ch*HWSZ;
                v = p[gy*WW + gx];
            }
            s_in[ci][r][c] = v;
        }
        // weights: [ci][k][oc] layout, 8*9*16 = 1152 entries
        for (int idx = tid; idx < 8*9*16; idx += 128) {
            int ci = idx / (9*16);
            int k  = (idx / 16) % 9;
            int oc = idx % 16;
            int o = ocBase + oc;
            float v = 0.f;
            if (o < Cout) v = w[((size_t)o*Cin + (cb+ci))*9 + k];
            s_w[ci][k][oc] = v;
        }
        __syncthreads();

        #pragma unroll
        for (int ci = 0; ci < 8; ci++) {
            #pragma unroll
            for (int kk = 0; kk < 9; kk++) {
                const int ky = kk / 3, kx = kk % 3;
                float v0 = s_in[ci][ty      + ky][tx + kx];
                float v1 = s_in[ci][ty + 4  + ky][tx + kx];
                float v2 = s_in[ci][ty + 8  + ky][tx + kx];
                float v3 = s_in[ci][ty + 12 + ky][tx + kx];
                unsigned long long v0p, v1p, v2p, v3p;
                PACK2(v0p, v0); PACK2(v1p, v1); PACK2(v2p, v2); PACK2(v3p, v3);
                const ulonglong2* wp = (const ulonglong2*)&s_w[ci][kk][0];
                #pragma unroll
                for (int q = 0; q < 4; q++) {
                    ulonglong2 wv = wp[q];       // oc pairs (4q,4q+1) and (4q+2,4q+3)
                    FMA2(accp[0][q*2  ], v0p, wv.x);
                    FMA2(accp[0][q*2+1], v0p, wv.y);
                    FMA2(accp[1][q*2  ], v1p, wv.x);
                    FMA2(accp[1][q*2+1], v1p, wv.y);
                    FMA2(accp[2][q*2  ], v2p, wv.x);
                    FMA2(accp[2][q*2+1], v2p, wv.y);
                    FMA2(accp[3][q*2  ], v3p, wv.x);
                    FMA2(accp[3][q*2+1], v3p, wv.y);
                }
            }
        }
        __syncthreads();
    }

    // unpack accumulators
    float acc[4][16];
    #pragma unroll
    for (int r = 0; r < 4; r++)
        #pragma unroll
        for (int j = 0; j < 8; j++) {
            unsigned int lo, hi;
            UNPACK2(lo, hi, accp[r][j]);
            acc[r][j*2    ] = __uint_as_float(lo);
            acc[r][j*2 + 1] = __uint_as_float(hi);
        }

    int gx = ox0 + tx;
    float* ob;
    if (outMode == 1) ob = ext_out + (size_t)(b*5 + fi) * 3 * HWSZ;
    else              ob = scratch_ptr(outSel) + (size_t)eb * Cout * HWSZ;

    #pragma unroll
    for (int oc = 0; oc < 16; oc++) {
        int o = ocBase + oc;
        if (o < Cout) {
            float bv = bias[o];
            #pragma unroll
            for (int r = 0; r < 4; r++) {
                int gy = oy0 + ty + r*4;
                ob[(size_t)o*HWSZ + gy*WW + gx] = acc[r][oc] + bv;
            }
        }
    }
}

// ---------------- deformable conv (dg=8, Cg=8, K=3), smem weights + f32x2 FMA ----------------
// 256 threads, 16x16 pixel tile (one pixel per thread)
// xMode: 0 = x = scratch[xSel] + eb*64*HW ; 1 = x is supp read from pf (ext_x)
__global__ void __launch_bounds__(256) dconv_kernel(
    const float* __restrict__ ext_x,
    const float* __restrict__ bias,
    int xMode, int xSel, int wIdx, int outSel)
{
    __shared__ __align__(16) float s_w[72*64];  // one group's weight slab, 18 KB

    int tid = threadIdx.x;
    int tx = tid & 15, ty = tid >> 4;          // 16 x 16 tile
    int eb = blockIdx.z;
    int b, fi; eb_map(eb, b, fi);
    int gx = blockIdx.x * 16 + tx;
    int gy = blockIdx.y * 16 + ty;
    int p = gy * WW + gx;

    const float* x = (xMode == 1) ? ext_x + (size_t)(b*5 + fi) * CF * HWSZ
                                  : scratch_ptr(xSel) + (size_t)eb * CF * HWSZ;
    const float* off = g_off + (size_t)eb * COFF * HWSZ + p;
    const float* wT  = g_wT + (size_t)wIdx * WSTEP;   // [(ci*9+k)*64 + o]

    unsigned long long accp[32];
    #pragma unroll
    for (int o = 0; o < 32; o++) accp[o] = 0ULL;

    #pragma unroll 1
    for (int g = 0; g < 8; g++) {
        // stage wT rows [g*72, g*72+72) x 64 into smem (1152 float4)
        __syncthreads();
        {
            const float4* src = (const float4*)(wT + (size_t)g * 72 * 64);
            float4* dst = (float4*)s_w;
            for (int i = tid; i < 1152; i += 256) dst[i] = src[i];
        }
        __syncthreads();

        #pragma unroll 1
        for (int k = 0; k < 9; k++) {
            float oy = off[(size_t)((g*9 + k)*2 + 0) * HWSZ];
            float ox = off[(size_t)((g*9 + k)*2 + 1) * HWSZ];
            float py = (float)gy + (float)(k/3 - 1) + oy;
            float px = (float)gx + (float)(k%3 - 1) + ox;
            float fy = floorf(py), fx = floorf(px);
            float wy = py - fy,  wx = px - fx;
            int iy0 = (int)fy, ix0 = (int)fx;
            int iy1 = iy0 + 1, ix1 = ix0 + 1;
            float my0 = (iy0 >= 0 && iy0 < HH) ? 1.f : 0.f;
            float my1 = (iy1 >= 0 && iy1 < HH) ? 1.f : 0.f;
            float mx0 = (ix0 >= 0 && ix0 < WW) ? 1.f : 0.f;
            float mx1 = (ix1 >= 0 && ix1 < WW) ? 1.f : 0.f;
            int cy0 = min(max(iy0, 0), HH-1);
            int cy1 = min(max(iy1, 0), HH-1);
            int cx0 = min(max(ix0, 0), WW-1);
            int cx1 = min(max(ix1, 0), WW-1);
            int p00 = cy0*WW + cx0, p01 = cy0*WW + cx1;
            int p10 = cy1*WW + cx0, p11 = cy1*WW + cx1;
            float w00 = (1.f - wy) * (1.f - wx) * my0 * mx0;
            float w01 = (1.f - wy) * wx         * my0 * mx1;
            float w10 = wy         * (1.f - wx) * my1 * mx0;
            float w11 = wy         * wx         * my1 * mx1;

            #pragma unroll
            for (int c = 0; c < 8; c++) {
                const float* ch = x + (size_t)(g*8 + c) * HWSZ;
                float s = ch[p00]*w00 + ch[p01]*w01 + ch[p10]*w10 + ch[p11]*w11;
                unsigned long long sp;
                PACK2(sp, s);
                const ulonglong2* wtc = (const ulonglong2*)(s_w + (c*9 + k) * 64);
                #pragma unroll
                for (int j = 0; j < 16; j++) {
                    ulonglong2 wv = wtc[j];      // o pairs (4j,4j+1) and (4j+2,4j+3)
                    FMA2(accp[j*2  ], sp, wv.x);
                    FMA2(accp[j*2+1], sp, wv.y);
                }
            }
        }
    }

    float* ob = scratch_ptr(outSel) + (size_t)eb * CF * HWSZ + p;
    #pragma unroll
    for (int j = 0; j < 32; j++) {
        unsigned int lo, hi;
        UNPACK2(lo, hi, accp[j]);
        ob[(size_t)(j*2    ) * HWSZ] = __uint_as_float(lo) + bias[j*2];
        ob[(size_t)(j*2 + 1) * HWSZ] = __uint_as_float(hi) + bias[j*2 + 1];
    }
}

// ---------------- dconv weight transpose: OIHW -> [(ci*9+k)][o], 4 at once ----------------
__global__ void wtrans_kernel(const float* __restrict__ w1, const float* __restrict__ w2,
                              const float* __restrict__ w3, const float* __restrict__ w4) {
    int i = blockIdx.x * 256 + threadIdx.x;
    int wIdx = blockIdx.y;
    const float* w = wIdx == 0 ? w1 : (wIdx == 1 ? w2 : (wIdx == 2 ? w3 : w4));
    if (i < 64*576) {
        int o = i / 576;
        int r = i % 576;
        g_wT[(size_t)wIdx*WSTEP + (size_t)r*64 + o] = w[i];
    }
}

// ---------------- center frame passthrough ----------------
__global__ void center_kernel(const float* __restrict__ xc, float* __restrict__ out) {
    int i = blockIdx.x * 256 + threadIdx.x;
    const int total = 2*3*HWSZ;
    if (i < total) {
        int b = i / (3*HWSZ);
        int r = i % (3*HWSZ);
        out[(size_t)(b*5 + 2)*3*HWSZ + r] = xc[i];
    }
}

// ---------------- launch (pure kernel launches; nothing else) ----------------
extern "C" void kernel_launch(void* const* d_in, const int* in_sizes, int n_in,
                              void* d_out, int out_size)
{
    const float* pf     = (const float*)d_in[0];
    const float* xc     = (const float*)d_in[1];
    const float* cr_w   = (const float*)d_in[2];
    const float* cr_b   = (const float*)d_in[3];
    const float* off1_w = (const float*)d_in[4];
    const float* off1_b = (const float*)d_in[5];
    const float* dc1_w  = (const float*)d_in[6];
    const float* dc1_b  = (const float*)d_in[7];
    const float* off2_w = (const float*)d_in[8];
    const float* off2_b = (const float*)d_in[9];
    const float* dc2_w  = (const float*)d_in[10];
    const float* dc2_b  = (const float*)d_in[11];
    const float* off3_w = (const float*)d_in[12];
    const float* off3_b = (const float*)d_in[13];
    const float* dc3_w  = (const float*)d_in[14];
    const float* dc3_b  = (const float*)d_in[15];
    const float* off4_w = (const float*)d_in[16];
    const float* off4_b = (const float*)d_in[17];
    const float* dc4_w  = (const float*)d_in[18];
    const float* dc4_b  = (const float*)d_in[19];
    const float* rec_w  = (const float*)d_in[20];
    const float* rec_b  = (const float*)d_in[21];
    float* out = (float*)d_out;

    dim3 tb(256);
    // transpose the 4 dconv weight tensors into g_wT (single launch)
    { dim3 g(144, 4); wtrans_kernel<<<g, tb>>>(dc1_w, dc2_w, dc3_w, dc4_w); }

    // center frame
    center_kernel<<<(2*3*HWSZ + 255)/256, tb>>>(xc, out);

    auto conv = [&](const float* ein, const float* w, const float* bsrc, float* eout,
                    int Cin, int Cout, int inMode, int outMode, int inSel, int outSel) {
        int ocg = (Cout + 15) >> 4;
        dim3 grid(WW/32, HH/16, EBN * ocg);
        conv3x3_kernel<<<grid, 128>>>(ein, w, bsrc, eout, Cin, Cout,
                                      inMode, outMode, inSel, outSel);
    };
    auto dconv = [&](const float* ex, const float* bsrc,
                     int xMode, int xSel, int wIdx, int outSel) {
        dim3 grid(WW/16, HH/16, EBN);
        dconv_kernel<<<grid, 256>>>(ex, bsrc, xMode, xSel, wIdx, outSel);
    };

    // fea0 = conv(concat(ref,supp))
    conv(pf, cr_w, cr_b, nullptr, 2*CF, CF, 1, 0, 0, 0);
    // off = off1(fea0); fea1 = dconv(fea0, off)
    conv(nullptr, off1_w, off1_b, nullptr, CF, COFF, 0, 0, 0, 2);
    dconv(nullptr, dc1_b, 0, 0, 0, 1);
    // off = off2(fea1); fea0 = dconv(fea1, off)
    conv(nullptr, off2_w, off2_b, nullptr, CF, COFF, 0, 0, 1, 2);
    dconv(nullptr, dc2_b, 0, 1, 1, 0);
    // off = off3(fea0); fea1 = dconv(supp, off)
    conv(nullptr, off3_w, off3_b, nullptr, CF, COFF, 0, 0, 0, 2);
    dconv(pf, dc3_b, 1, 0, 2, 1);
    // off = off4(fea1); fea0 = dconv(fea1, off)
    conv(nullptr, off4_w, off4_b, nullptr, CF, COFF, 0, 0, 1, 2);
    dconv(nullptr, dc4_b, 0, 1, 3, 0);
    // out = rec(fea0)
    conv(nullptr, rec_w, rec_b, out, CF, 3, 0, 1, 0, 0);
}

// round 15
// speedup vs baseline: 2.0751x; 1.1183x over previous
#include <cuda_runtime.h>
#include <cstddef>

#define HH 128
#define WW 128
#define HWSZ (HH*WW)
#define EBN 8      // B(2) * 4 non-center frames, processed concurrently
#define CF 64
#define COFF 144
#define WSTEP (CF*CF*9)

// packed fp32x2 FMA: d = a*b + d  (two independent fp32 FMAs, .rn, one FFMA2)
#define FMA2(d, a, b) \
    asm("fma.rn.f32x2 %0, %1, %2, %0;" : "+l"(d) : "l"(a), "l"(b))
#define PACK2(d, v) \
    asm("mov.b64 %0, {%1, %1};" : "=l"(d) : "r"(__float_as_uint(v)))
#define UNPACK2(lo, hi, v) \
    asm("mov.b64 {%0, %1}, %2;" : "=r"(lo), "=r"(hi) : "l"(v))

// ---------------- scratch (device globals; no allocation) ----------------
__device__ float g_fea0[(size_t)EBN*CF*HWSZ];   // 32 MB
__device__ float g_fea1[(size_t)EBN*CF*HWSZ];   // 32 MB
__device__ float g_off [(size_t)EBN*COFF*HWSZ]; // 72 MB
__device__ float g_wT  [4*WSTEP];               // transposed dconv weights

__device__ __forceinline__ float* scratch_ptr(int sel) {
    return sel == 0 ? g_fea0 : (sel == 1 ? g_fea1 : g_off);
}

// eb -> (b, frame)
__device__ __forceinline__ void eb_map(int eb, int& b, int& fi) {
    b = eb >> 2;
    int f = eb & 3;
    fi = f + (f >= 2 ? 1 : 0);   // frames {0,1,3,4}
}

// ---------------- 3x3 SAME conv: 32x16 tile, 128 threads, 4 px/thread ----------------
// weights staged as [ci][kk][oc]; inner loop uses packed f32x2 FMA over oc pairs
__global__ void __launch_bounds__(128) conv3x3_kernel(
    const float* __restrict__ ext_in,
    const float* __restrict__ w,
    const float* __restrict__ bias,
    float* __restrict__ ext_out,
    int Cin, int Cout, int inMode, int outMode, int inSel, int outSel)
{
    __shared__ float s_in[8][18][34];
    __shared__ __align__(16) float s_w[8][9][16];   // [ci][kk][oc]

    int tid = threadIdx.x;
    int tx = tid & 31, ty = tid >> 5;           // 32 x 4 threads, 4 rows/thread
    int ocg = (Cout + 15) >> 4;
    int eb = blockIdx.z / ocg;
    int ocBase = (blockIdx.z % ocg) << 4;
    int b, fi; eb_map(eb, b, fi);
    int ox0 = blockIdx.x * 32, oy0 = blockIdx.y * 16;

    const float* ref = nullptr; const float* supp = nullptr; const float* inb = nullptr;
    if (inMode == 1) {
        ref  = ext_in + (size_t)(b*5 + 2)  * CF * HWSZ;
        supp = ext_in + (size_t)(b*5 + fi) * CF * HWSZ;
    } else {
        inb = scratch_ptr(inSel) + (size_t)eb * Cin * HWSZ;
    }

    unsigned long long accp[4][8];
    #pragma unroll
    for (int r = 0; r < 4; r++)
        #pragma unroll
        for (int i = 0; i < 8; i++) accp[r][i] = 0ULL;

    for (int cb = 0; cb < Cin; cb += 8) {
        // cooperative load: 8 channels x (18 x 34) tile with zero-pad
        for (int idx = tid; idx < 8*18*34; idx += 128) {
            int ci = idx / (18*34);
            int rem = idx % (18*34);
            int r  = rem / 34;
            int c  = rem % 34;
            int gy = oy0 + r - 1;
            int gx = ox0 + c - 1;
            float v = 0.f;
            if (gy >= 0 && gy < HH && gx >= 0 && gx < WW) {
                int ch = cb + ci;
                const float* p;
                if (inMode == 1)
                    p = (ch < CF) ? (ref + (size_t)ch*HWSZ) : (supp + (size_t)(ch-CF)*HWSZ);
                else
                    p = inb + (size_t)ch*HWSZ;
                v = p[gy*WW + gx];
            }
            s_in[ci][r][c] = v;
        }
        // weights: [ci][k][oc] layout, 8*9*16 = 1152 entries
        for (int idx = tid; idx < 8*9*16; idx += 128) {
            int ci = idx / (9*16);
            int k  = (idx / 16) % 9;
            int oc = idx % 16;
            int o = ocBase + oc;
            float v = 0.f;
            if (o < Cout) v = w[((size_t)o*Cin + (cb+ci))*9 + k];
            s_w[ci][k][oc] = v;
        }
        __syncthreads();

        #pragma unroll
        for (int ci = 0; ci < 8; ci++) {
            #pragma unroll
            for (int kk = 0; kk < 9; kk++) {
                const int ky = kk / 3, kx = kk % 3;
                float v0 = s_in[ci][ty      + ky][tx + kx];
                float v1 = s_in[ci][ty + 4  + ky][tx + kx];
                float v2 = s_in[ci][ty + 8  + ky][tx + kx];
                float v3 = s_in[ci][ty + 12 + ky][tx + kx];
                unsigned long long v0p, v1p, v2p, v3p;
                PACK2(v0p, v0); PACK2(v1p, v1); PACK2(v2p, v2); PACK2(v3p, v3);
                const ulonglong2* wp = (const ulonglong2*)&s_w[ci][kk][0];
                #pragma unroll
                for (int q = 0; q < 4; q++) {
                    ulonglong2 wv = wp[q];       // oc pairs (4q,4q+1) and (4q+2,4q+3)
                    FMA2(accp[0][q*2  ], v0p, wv.x);
                    FMA2(accp[0][q*2+1], v0p, wv.y);
                    FMA2(accp[1][q*2  ], v1p, wv.x);
                    FMA2(accp[1][q*2+1], v1p, wv.y);
                    FMA2(accp[2][q*2  ], v2p, wv.x);
                    FMA2(accp[2][q*2+1], v2p, wv.y);
                    FMA2(accp[3][q*2  ], v3p, wv.x);
                    FMA2(accp[3][q*2+1], v3p, wv.y);
                }
            }
        }
        __syncthreads();
    }

    // unpack accumulators
    float acc[4][16];
    #pragma unroll
    for (int r = 0; r < 4; r++)
        #pragma unroll
        for (int j = 0; j < 8; j++) {
            unsigned int lo, hi;
            UNPACK2(lo, hi, accp[r][j]);
            acc[r][j*2    ] = __uint_as_float(lo);
            acc[r][j*2 + 1] = __uint_as_float(hi);
        }

    int gx = ox0 + tx;
    float* ob;
    if (outMode == 1) ob = ext_out + (size_t)(b*5 + fi) * 3 * HWSZ;
    else              ob = scratch_ptr(outSel) + (size_t)eb * Cout * HWSZ;

    #pragma unroll
    for (int oc = 0; oc < 16; oc++) {
        int o = ocBase + oc;
        if (o < Cout) {
            float bv = bias[o];
            #pragma unroll
            for (int r = 0; r < 4; r++) {
                int gy = oy0 + ty + r*4;
                ob[(size_t)o*HWSZ + gy*WW + gx] = acc[r][oc] + bv;
            }
        }
    }
}

// ---------------- deformable conv (dg=8, Cg=8, K=3), smem weights + f32x2 FMA ----------------
// 256 threads, 16x16 pixel tile; min 2 blocks/SM (reg cap 128) + offset prefetch pipeline
// xMode: 0 = x = scratch[xSel] + eb*64*HW ; 1 = x is supp read from pf (ext_x)
__global__ void __launch_bounds__(256, 2) dconv_kernel(
    const float* __restrict__ ext_x,
    const float* __restrict__ bias,
    int xMode, int xSel, int wIdx, int outSel)
{
    __shared__ __align__(16) float s_w[72*64];  // one group's weight slab, 18 KB

    int tid = threadIdx.x;
    int tx = tid & 15, ty = tid >> 4;          // 16 x 16 tile
    int eb = blockIdx.z;
    int b, fi; eb_map(eb, b, fi);
    int gx = blockIdx.x * 16 + tx;
    int gy = blockIdx.y * 16 + ty;
    int p = gy * WW + gx;

    const float* x = (xMode == 1) ? ext_x + (size_t)(b*5 + fi) * CF * HWSZ
                                  : scratch_ptr(xSel) + (size_t)eb * CF * HWSZ;
    const float* off = g_off + (size_t)eb * COFF * HWSZ + p;
    const float* wT  = g_wT + (size_t)wIdx * WSTEP;   // [(ci*9+k)*64 + o]

    unsigned long long accp[32];
    #pragma unroll
    for (int o = 0; o < 32; o++) accp[o] = 0ULL;

    // offset software pipeline: preload (g,k)=(0,0)
    float oy_n = off[0];
    float ox_n = off[(size_t)HWSZ];

    #pragma unroll 1
    for (int g = 0; g < 8; g++) {
        // stage wT rows [g*72, g*72+72) x 64 into smem (1152 float4)
        __syncthreads();
        {
            const float4* src = (const float4*)(wT + (size_t)g * 72 * 64);
            float4* dst = (float4*)s_w;
            for (int i = tid; i < 1152; i += 256) dst[i] = src[i];
        }
        __syncthreads();

        #pragma unroll 1
        for (int k = 0; k < 9; k++) {
            float oy = oy_n, ox = ox_n;
            int nk = g*9 + k + 1;
            if (nk < 72) {                        // preload next (g,k) offsets
                oy_n = off[(size_t)(2*nk    ) * HWSZ];
                ox_n = off[(size_t)(2*nk + 1) * HWSZ];
            }
            float py = (float)gy + (float)(k/3 - 1) + oy;
            float px = (float)gx + (float)(k%3 - 1) + ox;
            float fy = floorf(py), fx = floorf(px);
            float wy = py - fy,  wx = px - fx;
            int iy0 = (int)fy, ix0 = (int)fx;
            int iy1 = iy0 + 1, ix1 = ix0 + 1;
            float my0 = (iy0 >= 0 && iy0 < HH) ? 1.f : 0.f;
            float my1 = (iy1 >= 0 && iy1 < HH) ? 1.f : 0.f;
            float mx0 = (ix0 >= 0 && ix0 < WW) ? 1.f : 0.f;
            float mx1 = (ix1 >= 0 && ix1 < WW) ? 1.f : 0.f;
            int cy0 = min(max(iy0, 0), HH-1);
            int cy1 = min(max(iy1, 0), HH-1);
            int cx0 = min(max(ix0, 0), WW-1);
            int cx1 = min(max(ix1, 0), WW-1);
            int p00 = cy0*WW + cx0, p01 = cy0*WW + cx1;
            int p10 = cy1*WW + cx0, p11 = cy1*WW + cx1;
            float w00 = (1.f - wy) * (1.f - wx) * my0 * mx0;
            float w01 = (1.f - wy) * wx         * my0 * mx1;
            float w10 = wy         * (1.f - wx) * my1 * mx0;
            float w11 = wy         * wx         * my1 * mx1;

            #pragma unroll
            for (int c = 0; c < 8; c++) {
                const float* ch = x + (size_t)(g*8 + c) * HWSZ;
                float s = ch[p00]*w00 + ch[p01]*w01 + ch[p10]*w10 + ch[p11]*w11;
                unsigned long long sp;
                PACK2(sp, s);
                const ulonglong2* wtc = (const ulonglong2*)(s_w + (c*9 + k) * 64);
                #pragma unroll
                for (int j = 0; j < 16; j++) {
                    ulonglong2 wv = wtc[j];      // o pairs (4j,4j+1) and (4j+2,4j+3)
                    FMA2(accp[j*2  ], sp, wv.x);
                    FMA2(accp[j*2+1], sp, wv.y);
                }
            }
        }
    }

    float* ob = scratch_ptr(outSel) + (size_t)eb * CF * HWSZ + p;
    #pragma unroll
    for (int j = 0; j < 32; j++) {
        unsigned int lo, hi;
        UNPACK2(lo, hi, accp[j]);
        ob[(size_t)(j*2    ) * HWSZ] = __uint_as_float(lo) + bias[j*2];
        ob[(size_t)(j*2 + 1) * HWSZ] = __uint_as_float(hi) + bias[j*2 + 1];
    }
}

// ---------------- dconv weight transpose: OIHW -> [(ci*9+k)][o], 4 at once ----------------
__global__ void wtrans_kernel(const float* __restrict__ w1, const float* __restrict__ w2,
                              const float* __restrict__ w3, const float* __restrict__ w4) {
    int i = blockIdx.x * 256 + threadIdx.x;
    int wIdx = blockIdx.y;
    const float* w = wIdx == 0 ? w1 : (wIdx == 1 ? w2 : (wIdx == 2 ? w3 : w4));
    if (i < 64*576) {
        int o = i / 576;
        int r = i % 576;
        g_wT[(size_t)wIdx*WSTEP + (size_t)r*64 + o] = w[i];
    }
}

// ---------------- center frame passthrough ----------------
__global__ void center_kernel(const float* __restrict__ xc, float* __restrict__ out) {
    int i = blockIdx.x * 256 + threadIdx.x;
    const int total = 2*3*HWSZ;
    if (i < total) {
        int b = i / (3*HWSZ);
        int r = i % (3*HWSZ);
        out[(size_t)(b*5 + 2)*3*HWSZ + r] = xc[i];
    }
}

// ---------------- launch (pure kernel launches; nothing else) ----------------
extern "C" void kernel_launch(void* const* d_in, const int* in_sizes, int n_in,
                              void* d_out, int out_size)
{
    const float* pf     = (const float*)d_in[0];
    const float* xc     = (const float*)d_in[1];
    const float* cr_w   = (const float*)d_in[2];
    const float* cr_b   = (const float*)d_in[3];
    const float* off1_w = (const float*)d_in[4];
    const float* off1_b = (const float*)d_in[5];
    const float* dc1_w  = (const float*)d_in[6];
    const float* dc1_b  = (const float*)d_in[7];
    const float* off2_w = (const float*)d_in[8];
    const float* off2_b = (const float*)d_in[9];
    const float* dc2_w  = (const float*)d_in[10];
    const float* dc2_b  = (const float*)d_in[11];
    const float* off3_w = (const float*)d_in[12];
    const float* off3_b = (const float*)d_in[13];
    const float* dc3_w  = (const float*)d_in[14];
    const float* dc3_b  = (const float*)d_in[15];
    const float* off4_w = (const float*)d_in[16];
    const float* off4_b = (const float*)d_in[17];
    const float* dc4_w  = (const float*)d_in[18];
    const float* dc4_b  = (const float*)d_in[19];
    const float* rec_w  = (const float*)d_in[20];
    const float* rec_b  = (const float*)d_in[21];
    float* out = (float*)d_out;

    dim3 tb(256);
    // transpose the 4 dconv weight tensors into g_wT (single launch)
    { dim3 g(144, 4); wtrans_kernel<<<g, tb>>>(dc1_w, dc2_w, dc3_w, dc4_w); }

    // center frame
    center_kernel<<<(2*3*HWSZ + 255)/256, tb>>>(xc, out);

    auto conv = [&](const float* ein, const float* w, const float* bsrc, float* eout,
                    int Cin, int Cout, int inMode, int outMode, int inSel, int outSel) {
        int ocg = (Cout + 15) >> 4;
        dim3 grid(WW/32, HH/16, EBN * ocg);
        conv3x3_kernel<<<grid, 128>>>(ein, w, bsrc, eout, Cin, Cout,
                                      inMode, outMode, inSel, outSel);
    };
    auto dconv = [&](const float* ex, const float* bsrc,
                     int xMode, int xSel, int wIdx, int outSel) {
        dim3 grid(WW/16, HH/16, EBN);
        dconv_kernel<<<grid, 256>>>(ex, bsrc, xMode, xSel, wIdx, outSel);
    };

    // fea0 = conv(concat(ref,supp))
    conv(pf, cr_w, cr_b, nullptr, 2*CF, CF, 1, 0, 0, 0);
    // off = off1(fea0); fea1 = dconv(fea0, off)
    conv(nullptr, off1_w, off1_b, nullptr, CF, COFF, 0, 0, 0, 2);
    dconv(nullptr, dc1_b, 0, 0, 0, 1);
    // off = off2(fea1); fea0 = dconv(fea1, off)
    conv(nullptr, off2_w, off2_b, nullptr, CF, COFF, 0, 0, 1, 2);
    dconv(nullptr, dc2_b, 0, 1, 1, 0);
    // off = off3(fea0); fea1 = dconv(supp, off)
    conv(nullptr, off3_w, off3_b, nullptr, CF, COFF, 0, 0, 0, 2);
    dconv(pf, dc3_b, 1, 0, 2, 1);
    // off = off4(fea1); fea0 = dconv(fea1, off)
    conv(nullptr, off4_w, off4_b, nullptr, CF, COFF, 0, 0, 1, 2);
    dconv(nullptr, dc4_b, 0, 1, 3, 0);
    // out = rec(fea0)
    conv(nullptr, rec_w, rec_b, out, CF, 3, 0, 1, 0, 0);
}